// round 5
// baseline (speedup 1.0000x reference)
#include <cuda_runtime.h>

#define S      256
#define NB     128
#define L      256
#define NL     64
#define VOCAB  32000

typedef unsigned long long ull;

// K1 dynamic smem:
//   TsmU2 [16][256] ulonglong2 = 65536 B   (T tail: 4 states x 16 j each)
//   xs    [2][2][256] float    =  4096 B   (double-buffered state vec per chain)
//   part  [2][4][256] float    =  8192 B   (partials: [chain][h][state])
//   tok   [2][256] int         =  2048 B
#define SMEM1  (65536 + 4096 + 8192 + 2048)

// scratch
__device__ float g_fwd[L * NB * S];   // fprime[t][b][s]  (pre-e-multiply forward)
__device__ float g_bwd[L * NB * S];   // b[t][b][s]

__device__ __forceinline__ void ffma2(ull &a, ull b, ull c) {
    asm("fma.rn.f32x2 %0, %1, %2, %0;" : "+l"(a) : "l"(b), "l"(c));
}
__device__ __forceinline__ float hsum1(ull a) {
    float2 v = *reinterpret_cast<float2*>(&a);
    return v.x + v.y;
}

// ---------------------------------------------------------------------------
// K1: 128 CTAs x 256 threads, 2 chains per CTA. bid<64: forward for batches
// (2p, 2p+1); bid>=64: backward. Thread (h=tid>>6, u=tid&63) owns states
// {u, u+64, u+128, u+192} restricted to j in [64h, 64h+64). Per state:
// 48 T values in registers, 16 in smem. Packed fma.rn.f32x2 over j-pairs;
// quarter partials combined through smem.
// ---------------------------------------------------------------------------
__global__ __launch_bounds__(256, 1)
void hmm_scan_kernel(const void* __restrict__ sent_raw,
                     const float* __restrict__ emb,
                     const float* __restrict__ Tm)
{
    extern __shared__ char smem_raw[];
    ulonglong2* TsmU2 = (ulonglong2*)smem_raw;              // [16][256]
    float* xs   = (float*)(smem_raw + 65536);               // [p][c][256]
    float* part = (float*)(smem_raw + 65536 + 4096);        // [c][h][256]
    int*   tok  = (int*)  (smem_raw + 65536 + 4096 + 8192); // [c][256]
    __shared__ int s_i64;

    const int  tid = threadIdx.x;
    const int  h   = tid >> 6;           // j-quarter 0..3
    const int  u   = tid & 63;           // base state
    const int  j0  = h << 6;             // j range start
    const int  bid = blockIdx.x;
    const bool bwd = (bid >= 64);
    const int  b0  = (bid & 63) * 2;
    const int  b1  = b0 + 1;

    // --- detect sentences dtype (int64 vs int32) ---
    if (tid == 0) {
        const long long* s64 = (const long long*)sent_raw;
        int f = 1;
        for (int k = 0; k < 64; k++) {
            long long v = s64[k];
            if (v < 0 || v >= VOCAB) { f = 0; break; }
        }
        s_i64 = f;
    }
    __syncthreads();

    // --- tokens for both chains ---
    if (s_i64) {
        const long long* s64 = (const long long*)sent_raw;
        tok[tid]       = (int)s64[b0 * L + tid];
        tok[256 + tid] = (int)s64[b1 * L + tid];
    } else {
        const int* s32 = (const int*)sent_raw;
        tok[tid]       = s32[b0 * L + tid];
        tok[256 + tid] = s32[b1 * L + tid];
    }

    // --- T slices: 4 states x 64 j -> 48 in regs (24 ull), 16 in smem (4 u2) ---
    ull TrU[4][24];
    #pragma unroll
    for (int k = 0; k < 4; k++) {
        const int sk = u + (k << 6);
        if (!bwd) {
            const float4* row = (const float4*)(Tm + sk * S + j0);
            #pragma unroll
            for (int g = 0; g < 12; g++) ((float4*)TrU[k])[g] = row[g];
            #pragma unroll
            for (int g = 0; g < 4; g++)
                TsmU2[(k * 4 + g) * 256 + tid] = ((const ulonglong2*)row)[12 + g];
        } else {
            #pragma unroll
            for (int g = 0; g < 12; g++) {
                int j = j0 + 4 * g;
                ((float4*)TrU[k])[g] = make_float4(
                    Tm[(j + 0) * S + sk], Tm[(j + 1) * S + sk],
                    Tm[(j + 2) * S + sk], Tm[(j + 3) * S + sk]);
            }
            #pragma unroll
            for (int g = 0; g < 4; g++) {
                int j = j0 + 48 + 4 * g;
                float4 f4 = make_float4(
                    Tm[(j + 0) * S + sk], Tm[(j + 1) * S + sk],
                    Tm[(j + 2) * S + sk], Tm[(j + 3) * S + sk]);
                TsmU2[(k * 4 + g) * 256 + tid] = *reinterpret_cast<ulonglong2*>(&f4);
            }
        }
    }

    float* outg = bwd ? g_bwd : g_fwd;

    // --- step 0 ---
    const int t0 = bwd ? (L - 1) : 0;
    {
        float e0 = emb[tok[t0] * S + tid];
        float e1 = emb[tok[256 + t0] * S + tid];
        if (!bwd) {
            outg[(t0 * NB + b0) * S + tid] = 1.0f;    // fprime[0] = 1
            outg[(t0 * NB + b1) * S + tid] = 1.0f;
        } else {
            outg[(t0 * NB + b0) * S + tid] = e0;      // b[L-1] = e[L-1]
            outg[(t0 * NB + b1) * S + tid] = e1;
        }
        xs[tid]       = e0;
        xs[256 + tid] = e1;
    }
    __syncthreads();

    const int dt = bwd ? -1 : 1;
    int t = t0;
    int p = 0;

    for (int step = 1; step < L; step++) {
        t += dt;
        // e prefetch: consumed only after the mat-vec + barrier
        float en0 = emb[tok[t] * S + tid];
        float en1 = emb[tok[256 + t] * S + tid];

        const ulonglong2* X0 = (const ulonglong2*)(xs + p * 512 + j0);
        const ulonglong2* X1 = (const ulonglong2*)(xs + p * 512 + 256 + j0);

        ull acc[4][2];
        #pragma unroll
        for (int k = 0; k < 4; k++) { acc[k][0] = 0ULL; acc[k][1] = 0ULL; }

        #pragma unroll
        for (int g = 0; g < 12; g++) {
            ulonglong2 x0 = X0[g];
            ulonglong2 x1 = X1[g];
            #pragma unroll
            for (int k = 0; k < 4; k++) {
                ffma2(acc[k][0], TrU[k][2 * g],     x0.x);
                ffma2(acc[k][0], TrU[k][2 * g + 1], x0.y);
                ffma2(acc[k][1], TrU[k][2 * g],     x1.x);
                ffma2(acc[k][1], TrU[k][2 * g + 1], x1.y);
            }
        }
        #pragma unroll
        for (int g = 0; g < 4; g++) {
            ulonglong2 x0 = X0[12 + g];
            ulonglong2 x1 = X1[12 + g];
            #pragma unroll
            for (int k = 0; k < 4; k++) {
                ulonglong2 tk = TsmU2[(k * 4 + g) * 256 + tid];
                ffma2(acc[k][0], tk.x, x0.x);
                ffma2(acc[k][0], tk.y, x0.y);
                ffma2(acc[k][1], tk.x, x1.x);
                ffma2(acc[k][1], tk.y, x1.y);
            }
        }

        // quarter partials: part[c][h][s]
        #pragma unroll
        for (int k = 0; k < 4; k++) {
            part[h * 256 + u + (k << 6)]        = hsum1(acc[k][0]);
            part[1024 + h * 256 + u + (k << 6)] = hsum1(acc[k][1]);
        }
        __syncthreads();

        // combine: thread tid handles state tid, both chains
        float s0 = (part[tid] + part[256 + tid]) + (part[512 + tid] + part[768 + tid]);
        float s1 = (part[1024 + tid] + part[1280 + tid]) + (part[1536 + tid] + part[1792 + tid]);
        float nx0 = s0 * en0;
        float nx1 = s1 * en1;

        if (!bwd) {
            outg[(t * NB + b0) * S + tid] = s0;   // fprime
            outg[(t * NB + b1) * S + tid] = s1;
        } else {
            outg[(t * NB + b0) * S + tid] = nx0;  // b
            outg[(t * NB + b1) * S + tid] = nx1;
        }

        p ^= 1;
        xs[p * 512 + tid]       = nx0;
        xs[p * 512 + 256 + tid] = nx1;
        __syncthreads();
    }
}

// ---------------------------------------------------------------------------
// K2: score[b][t][n] = sum_s fprime[t][b][s] * b[t][b][s] * O[s][n]
// (unchanged — known good at ~39.6 us)
// ---------------------------------------------------------------------------
__global__ __launch_bounds__(256, 4)
void hmm_proj_kernel(const float* __restrict__ Om, float* __restrict__ outp)
{
    __shared__ float esm[64 * 68];
    __shared__ float osm[64 * 64];

    const int tid = threadIdx.x;
    const int r0  = blockIdx.x * 64;
    const int rg  = tid >> 4;
    const int cg  = tid & 15;

    float4 acc0 = make_float4(0.f, 0.f, 0.f, 0.f);
    float4 acc1 = make_float4(0.f, 0.f, 0.f, 0.f);
    float4 acc2 = make_float4(0.f, 0.f, 0.f, 0.f);
    float4 acc3 = make_float4(0.f, 0.f, 0.f, 0.f);

    for (int s0 = 0; s0 < S; s0 += 64) {
        if (s0) __syncthreads();
        #pragma unroll
        for (int k = 0; k < 4; k++) {
            int id4 = k * 256 + tid;
            int rr  = id4 >> 4;
            int ss  = (id4 & 15) * 4;
            int r   = r0 + rr;
            float4 fv = *(const float4*)&g_fwd[r * S + s0 + ss];
            float4 bv = *(const float4*)&g_bwd[r * S + s0 + ss];
            float4 ev = make_float4(fv.x * bv.x, fv.y * bv.y, fv.z * bv.z, fv.w * bv.w);
            *(float4*)&esm[rr * 68 + ss] = ev;
        }
        #pragma unroll
        for (int k = 0; k < 4; k++) {
            int id4 = k * 256 + tid;
            int ss  = id4 >> 4;
            int n   = (id4 & 15) * 4;
            *(float4*)&osm[ss * 64 + n] = *(const float4*)&Om[(s0 + ss) * NL + n];
        }
        __syncthreads();

        #pragma unroll 8
        for (int sc = 0; sc < 64; sc++) {
            float4 ov = *(const float4*)&osm[sc * 64 + cg * 4];
            float e0 = esm[(rg * 4 + 0) * 68 + sc];
            float e1 = esm[(rg * 4 + 1) * 68 + sc];
            float e2 = esm[(rg * 4 + 2) * 68 + sc];
            float e3 = esm[(rg * 4 + 3) * 68 + sc];
            acc0.x += e0 * ov.x; acc0.y += e0 * ov.y; acc0.z += e0 * ov.z; acc0.w += e0 * ov.w;
            acc1.x += e1 * ov.x; acc1.y += e1 * ov.y; acc1.z += e1 * ov.z; acc1.w += e1 * ov.w;
            acc2.x += e2 * ov.x; acc2.y += e2 * ov.y; acc2.z += e2 * ov.z; acc2.w += e2 * ov.w;
            acc3.x += e3 * ov.x; acc3.y += e3 * ov.y; acc3.z += e3 * ov.z; acc3.w += e3 * ov.w;
        }
    }

    #pragma unroll
    for (int k = 0; k < 4; k++) {
        int r  = r0 + rg * 4 + k;
        int t  = r >> 7;
        int bb = r & 127;
        float4 v = (k == 0) ? acc0 : (k == 1) ? acc1 : (k == 2) ? acc2 : acc3;
        *(float4*)&outp[(bb * L + t) * NL + cg * 4] = v;
    }
}

extern "C" void kernel_launch(void* const* d_in, const int* in_sizes, int n_in,
                              void* d_out, int out_size)
{
    (void)in_sizes; (void)n_in; (void)out_size;
    const void*  sent = d_in[0];
    const float* emb  = (const float*)d_in[1];
    const float* Tm   = (const float*)d_in[2];
    const float* Om   = (const float*)d_in[3];
    float* outp = (float*)d_out;

    cudaFuncSetAttribute(hmm_scan_kernel,
                         cudaFuncAttributeMaxDynamicSharedMemorySize, SMEM1);

    hmm_scan_kernel<<<128, 256, SMEM1>>>(sent, emb, Tm);
    hmm_proj_kernel<<<512, 256>>>(Om, outp);
}